// round 11
// baseline (speedup 1.0000x reference)
#include <cuda_runtime.h>
#include <cuda_bf16.h>
#include <cstdint>

// Problem constants (fixed shapes per reference)
#define NNODES   30000
#define RREL     8
#define NBASES   30
#define IN_DIM   256
#define Z_DIM    128
#define HID      256           // Z_DIM*2
#define NEDGES   480000        // N*16
#define NSEG     (NNODES*RREL) // 240000
#define KAGG     (RREL*256)    // 2048

// ---------------- scratch (device globals; referenced DIRECTLY by kernels) ---
__device__ __align__(16) float g_M  [(size_t)NNODES * RREL * 256];  // 245.76 MB
__device__ __align__(16) float g_Z1 [(size_t)NNODES * HID];
__device__ __align__(16) float g_W1 [(size_t)RREL * IN_DIM * HID];  // [2048, 256]
__device__ __align__(16) float g_W2 [(size_t)RREL * HID * Z_DIM];   // [2048, 128]
__device__ __align__(16) float g_inv[NSEG];
__device__ int   g_cnt[NSEG];
__device__ int   g_src[NEDGES];
__device__ int   g_seg[NEDGES];
__device__ int   g_is64;

// ---------------- dtype autodetect (int32 vs int64 edge arrays) --------------
__global__ void detect_dtype(const unsigned* __restrict__ et_words) {
    int is64 = 1;
    for (int i = 0; i < 64; ++i) {
        unsigned lo = et_words[2 * i];
        unsigned hi = et_words[2 * i + 1];
        if (hi != 0u || lo >= (unsigned)RREL) { is64 = 0; break; }
    }
    g_is64 = is64;
}

// ---------------- utility kernels --------------------------------------------
__global__ void zero_M(int also_cnt) {
    size_t i = (size_t)blockIdx.x * 256 + threadIdx.x;
    size_t n4 = (size_t)NNODES * RREL * 64;
    if (i < n4) ((float4*)g_M)[i] = make_float4(0.f, 0.f, 0.f, 0.f);
    if (also_cnt && i < NSEG) g_cnt[i] = 0;
}

__global__ void prep_edges(const void* __restrict__ ei_raw,
                           const void* __restrict__ et_raw) {
    int e = blockIdx.x * 256 + threadIdx.x;
    if (e >= NEDGES) return;
    int s, d, t;
    if (g_is64) {
        const long long* ei = (const long long*)ei_raw;
        const long long* et = (const long long*)et_raw;
        s = (int)ei[e]; d = (int)ei[NEDGES + e]; t = (int)et[e];
    } else {
        const int* ei = (const int*)ei_raw;
        const int* et = (const int*)et_raw;
        s = ei[e];      d = ei[NEDGES + e];      t = et[e];
    }
    s = min(max(s, 0), NNODES - 1);
    d = min(max(d, 0), NNODES - 1);
    t = min(max(t, 0), RREL - 1);
    g_src[e] = s;
    int g = d * RREL + t;
    g_seg[e] = g;
    atomicAdd(&g_cnt[g], 1);
}

__global__ void make_inv() {
    int i = blockIdx.x * 256 + threadIdx.x;
    if (i < NSEG) g_inv[i] = 1.0f / fmaxf((float)g_cnt[i], 1.0f);
}

// W[r, io] = sum_b comp[r,b] * bases[b, io]
__global__ void build_W(const float* __restrict__ bases,
                        const float* __restrict__ comp,
                        int IO, int layer) {
    float* W = (layer == 1) ? g_W1 : g_W2;
    __shared__ float sc[RREL * NBASES];
    if (threadIdx.x < RREL * NBASES) sc[threadIdx.x] = comp[threadIdx.x];
    __syncthreads();
    int io = blockIdx.x * 256 + threadIdx.x;
    if (io >= IO) return;
    float acc[RREL];
#pragma unroll
    for (int r = 0; r < RREL; ++r) acc[r] = 0.f;
#pragma unroll 5
    for (int b = 0; b < NBASES; ++b) {
        float bv = bases[(size_t)b * IO + io];
#pragma unroll
        for (int r = 0; r < RREL; ++r) acc[r] += sc[r * NBASES + b] * bv;
    }
#pragma unroll
    for (int r = 0; r < RREL; ++r) W[(size_t)r * IO + io] = acc[r];
}

// g_M[seg[e], :] += inv[seg[e]] * feat[src[e], :]   (R9 scatter — measured fast)
__global__ void scatter_edges(const float* __restrict__ x, int use_z1) {
    const float* feat = use_z1 ? g_Z1 : x;
    int e = blockIdx.x * 4 + (threadIdx.x >> 6);
    int lane = threadIdx.x & 63;
    if (e >= NEDGES) return;
    int sg = g_seg[e];
    float sc = g_inv[sg];
    float4 v = *(const float4*)(feat + (size_t)g_src[e] * 256 + lane * 4);
    float* dst = g_M + (size_t)sg * 256 + lane * 4;
    atomicAdd(dst + 0, v.x * sc);
    atomicAdd(dst + 1, v.y * sc);
    atomicAdd(dst + 2, v.z * sc);
    atomicAdd(dst + 3, v.w * sc);
}

// ---------------- tensor-core dual-GEMM (bf16 3-term split) ------------------
// C[n,:] = g_M[n,:2048] @ W + A2[n,:256] @ root + bias  (+leaky for layer 1)
// BM=128, BN=128, BK=32, 256 threads = 8 warps (4 M x 2 N), warp tile 32x64.
// mma.sync.m16n8k16 bf16; fp32 = hi + lo bf16; C += Ah*Bh + Ah*Bl + Al*Bh.
#define BM 128
#define BN 128
#define BK 32
#define SAPAD 4
#define SSTR (BK + SAPAD)   // 36 elements, 72B row stride

#define MMA_BF16(d, a, b0v, b1v)                                            \
    asm volatile(                                                           \
        "mma.sync.aligned.m16n8k16.row.col.f32.bf16.bf16.f32 "              \
        "{%0,%1,%2,%3}, {%4,%5,%6,%7}, {%8,%9}, {%0,%1,%2,%3};"             \
        : "+f"(d[0]), "+f"(d[1]), "+f"(d[2]), "+f"(d[3])                    \
        : "r"(a[0]), "r"(a[1]), "r"(a[2]), "r"(a[3]), "r"(b0v), "r"(b1v))

__device__ __forceinline__ void split_bf(float v, __nv_bfloat16& h, __nv_bfloat16& l) {
    h = __float2bfloat16(v);
    l = __float2bfloat16(v - __bfloat162float(h));
}

__global__ __launch_bounds__(256)
void gemm_tc(int layer, const float* __restrict__ xin,
             const float* __restrict__ root, const float* __restrict__ bias,
             float* __restrict__ outp, int ncols)
{
    __shared__ __align__(16) __nv_bfloat16 sAh[BM][SSTR];
    __shared__ __align__(16) __nv_bfloat16 sAl[BM][SSTR];
    __shared__ __align__(16) __nv_bfloat16 sBh[BN][SSTR];   // [n][k] (k contiguous)
    __shared__ __align__(16) __nv_bfloat16 sBl[BN][SSTR];

    const float* B1 = (layer == 1) ? g_W1 : g_W2;
    const float* A2 = (layer == 1) ? xin  : g_Z1;
    float*       C  = (layer == 1) ? g_Z1 : outp;
    const int leaky = (layer == 1);

    const int tid  = threadIdx.x;
    const int wid  = tid >> 5;
    const int lane = tid & 31;
    const int qg   = lane >> 2;    // group id 0..7
    const int tg   = lane & 3;     // thread-in-group 0..3
    const int wm   = (wid & 3) * 32;   // warp M offset in tile
    const int wn   = (wid >> 2) * 64;  // warp N offset in tile
    const int row0 = blockIdx.x * BM;
    const int col0 = blockIdx.y * BN;

    float acc[2][8][4];
#pragma unroll
    for (int mt = 0; mt < 2; ++mt)
#pragma unroll
        for (int nt = 0; nt < 8; ++nt)
#pragma unroll
            for (int i = 0; i < 4; ++i) acc[mt][nt][i] = 0.f;

    for (int phase = 0; phase < 2; ++phase) {
        const float* A = phase ? A2 : g_M;
        const float* B = phase ? root : B1;
        const int K = phase ? 256 : KAGG;

        for (int k0 = 0; k0 < K; k0 += BK) {
            // ---- load + split A tile: BM x BK, row-major -------------------
#pragma unroll
            for (int i = 0; i < 4; ++i) {
                int idx = tid + i * 256;      // 0..1023 float4 slots
                int ar  = idx >> 3;           // 0..127
                int ac  = (idx & 7) * 4;      // 0..28
                int grow = row0 + ar;
                float4 v = make_float4(0.f, 0.f, 0.f, 0.f);
                if (grow < NNODES)
                    v = *(const float4*)&A[(size_t)grow * K + k0 + ac];
                __nv_bfloat16 h0, h1, h2, h3, l0, l1, l2, l3;
                split_bf(v.x, h0, l0); split_bf(v.y, h1, l1);
                split_bf(v.z, h2, l2); split_bf(v.w, h3, l3);
                *(__nv_bfloat162*)&sAh[ar][ac]     = __nv_bfloat162(h0, h1);
                *(__nv_bfloat162*)&sAh[ar][ac + 2] = __nv_bfloat162(h2, h3);
                *(__nv_bfloat162*)&sAl[ar][ac]     = __nv_bfloat162(l0, l1);
                *(__nv_bfloat162*)&sAl[ar][ac + 2] = __nv_bfloat162(l2, l3);
            }
            // ---- load + split + transpose B tile: BK x BN -> sB[n][k] ------
#pragma unroll
            for (int i = 0; i < 4; ++i) {
                int idx = tid + i * 256;
                int bk  = idx >> 5;           // 0..31
                int bc  = (idx & 31) * 4;     // 0..124
                float4 v = *(const float4*)&B[(size_t)(k0 + bk) * ncols + col0 + bc];
                __nv_bfloat16 h, l;
                split_bf(v.x, h, l); sBh[bc + 0][bk] = h; sBl[bc + 0][bk] = l;
                split_bf(v.y, h, l); sBh[bc + 1][bk] = h; sBl[bc + 1][bk] = l;
                split_bf(v.z, h, l); sBh[bc + 2][bk] = h; sBl[bc + 2][bk] = l;
                split_bf(v.w, h, l); sBh[bc + 3][bk] = h; sBl[bc + 3][bk] = l;
            }
            __syncthreads();

            // ---- compute: 2 k-tiles of 16 ----------------------------------
#pragma unroll
            for (int kt = 0; kt < 2; ++kt) {
                const int kk = kt * 16 + 2 * tg;
                uint32_t ah[2][4], al[2][4];
#pragma unroll
                for (int mt = 0; mt < 2; ++mt) {
                    int r = wm + mt * 16 + qg;
                    ah[mt][0] = *(const uint32_t*)&sAh[r][kk];
                    ah[mt][1] = *(const uint32_t*)&sAh[r + 8][kk];
                    ah[mt][2] = *(const uint32_t*)&sAh[r][kk + 8];
                    ah[mt][3] = *(const uint32_t*)&sAh[r + 8][kk + 8];
                    al[mt][0] = *(const uint32_t*)&sAl[r][kk];
                    al[mt][1] = *(const uint32_t*)&sAl[r + 8][kk];
                    al[mt][2] = *(const uint32_t*)&sAl[r][kk + 8];
                    al[mt][3] = *(const uint32_t*)&sAl[r + 8][kk + 8];
                }
#pragma unroll
                for (int nt = 0; nt < 8; ++nt) {
                    int n = wn + nt * 8 + qg;
                    uint32_t bh0 = *(const uint32_t*)&sBh[n][kk];
                    uint32_t bh1 = *(const uint32_t*)&sBh[n][kk + 8];
                    uint32_t bl0 = *(const uint32_t*)&sBl[n][kk];
                    uint32_t bl1 = *(const uint32_t*)&sBl[n][kk + 8];
#pragma unroll
                    for (int mt = 0; mt < 2; ++mt) {
                        MMA_BF16(acc[mt][nt], ah[mt], bh0, bh1);
                        MMA_BF16(acc[mt][nt], ah[mt], bl0, bl1);
                        MMA_BF16(acc[mt][nt], al[mt], bh0, bh1);
                    }
                }
            }
            __syncthreads();
        }
    }

    // ---- epilogue: bias + optional leaky, fragment-mapped stores ------------
#pragma unroll
    for (int mt = 0; mt < 2; ++mt) {
        int r0 = row0 + wm + mt * 16 + qg;
#pragma unroll
        for (int nt = 0; nt < 8; ++nt) {
            int c = col0 + wn + nt * 8 + 2 * tg;
            float b0 = bias[c], b1 = bias[c + 1];
            float v0 = acc[mt][nt][0] + b0;
            float v1 = acc[mt][nt][1] + b1;
            float v2 = acc[mt][nt][2] + b0;
            float v3 = acc[mt][nt][3] + b1;
            if (leaky) {
                v0 = v0 > 0.f ? v0 : 0.01f * v0;
                v1 = v1 > 0.f ? v1 : 0.01f * v1;
                v2 = v2 > 0.f ? v2 : 0.01f * v2;
                v3 = v3 > 0.f ? v3 : 0.01f * v3;
            }
            if (r0 < NNODES) {
                C[(size_t)r0 * ncols + c]     = v0;
                C[(size_t)r0 * ncols + c + 1] = v1;
            }
            if (r0 + 8 < NNODES) {
                C[(size_t)(r0 + 8) * ncols + c]     = v2;
                C[(size_t)(r0 + 8) * ncols + c + 1] = v3;
            }
        }
    }
}

// ---------------- host: robust input binding by element count ----------------
static const void* find_in(void* const* d_in, const int* sz, int n_in,
                           int want, int occ, int fallback_idx) {
    int seen = 0;
    for (int i = 0; i < n_in; ++i) {
        if (sz[i] == want) {
            if (seen == occ) return d_in[i];
            ++seen;
        }
    }
    return d_in[fallback_idx];
}

extern "C" void kernel_launch(void* const* d_in, const int* in_sizes, int n_in,
                              void* d_out, int out_size) {
    const float* x      = (const float*)find_in(d_in, in_sizes, n_in, NNODES * IN_DIM,       0, 0);
    const void*  ei     =               find_in(d_in, in_sizes, n_in, 2 * NEDGES,            0, 1);
    const void*  et     =               find_in(d_in, in_sizes, n_in, NEDGES,                0, 2);
    const float* bases1 = (const float*)find_in(d_in, in_sizes, n_in, NBASES * IN_DIM * HID, 0, 3);
    const float* comp1  = (const float*)find_in(d_in, in_sizes, n_in, RREL * NBASES,         0, 4);
    const float* root1  = (const float*)find_in(d_in, in_sizes, n_in, IN_DIM * HID,          0, 5);
    const float* bias1  = (const float*)find_in(d_in, in_sizes, n_in, HID,                   0, 6);
    const float* bases2 = (const float*)find_in(d_in, in_sizes, n_in, NBASES * HID * Z_DIM,  0, 7);
    const float* comp2  = (const float*)find_in(d_in, in_sizes, n_in, RREL * NBASES,         1, 8);
    const float* root2  = (const float*)find_in(d_in, in_sizes, n_in, HID * Z_DIM,           0, 9);
    const float* bias2  = (const float*)find_in(d_in, in_sizes, n_in, Z_DIM,                 0, 10);
    float* out = (float*)d_out;

    const int n4 = NNODES * RREL * 64;          // float4 count of g_M
    const int gZ = (n4 + 255) / 256;

    // prep
    detect_dtype<<<1, 1>>>((const unsigned*)et);
    zero_M<<<gZ, 256>>>(/*also_cnt=*/1);
    prep_edges<<<(NEDGES + 255) / 256, 256>>>(ei, et);
    make_inv<<<(NSEG + 255) / 256, 256>>>();
    build_W<<<(IN_DIM * HID + 255) / 256, 256>>>(bases1, comp1, IN_DIM * HID, 1);
    build_W<<<(HID * Z_DIM + 255) / 256, 256>>>(bases2, comp2, HID * Z_DIM, 2);

    // layer 1: M = scatter(x); Z1 = M@W1 + x@root1 + bias1; leaky
    scatter_edges<<<NEDGES / 4, 256>>>(x, /*use_z1=*/0);
    {
        dim3 grid((NNODES + BM - 1) / BM, HID / BN);
        gemm_tc<<<grid, 256>>>(1, x, root1, bias1, out, HID);
    }

    // layer 2: M = scatter(Z1); out = M@W2 + Z1@root2 + bias2
    zero_M<<<gZ, 256>>>(/*also_cnt=*/0);
    scatter_edges<<<NEDGES / 4, 256>>>(x, /*use_z1=*/1);
    {
        dim3 grid((NNODES + BM - 1) / BM, Z_DIM / BN);
        gemm_tc<<<grid, 256>>>(2, x, root2, bias2, out, Z_DIM);
    }
}

// round 14
// speedup vs baseline: 2.2777x; 2.2777x over previous
#include <cuda_runtime.h>
#include <cuda_bf16.h>
#include <cstdint>

// Problem constants
#define NNODES   30000
#define RREL     8
#define NBASES   30
#define IN_DIM   256
#define Z_DIM    128
#define HID      256
#define NEDGES   480000
#define NSEG     (NNODES*RREL)
#define KAGG     (RREL*256)        // 2048

// ---------------- device scratch ---------------------------------------------
__device__ __align__(16) float g_M [(size_t)NNODES * RREL * 256];   // 245.76 MB
__device__ __align__(16) float g_Z1[(size_t)NNODES * HID];
__device__ __align__(16) float g_inv[NSEG];
__device__ int g_cnt[NSEG], g_src[NEDGES], g_seg[NEDGES], g_is64;
// pre-split transposed weights: [out][K], K-major bf16
__device__ __align__(16) __nv_bfloat16 g_W1h[256*2048], g_W1l[256*2048];
__device__ __align__(16) __nv_bfloat16 g_W2h[128*2048], g_W2l[128*2048];
__device__ __align__(16) __nv_bfloat16 g_R1h[256*256],  g_R1l[256*256];
__device__ __align__(16) __nv_bfloat16 g_R2h[128*256],  g_R2l[128*256];

__device__ __forceinline__ void split_bf(float v, __nv_bfloat16& h, __nv_bfloat16& l) {
    h = __float2bfloat16(v);
    l = __float2bfloat16(v - __bfloat162float(h));
}
__device__ __forceinline__ uint32_t smem_u32(const void* p) {
    uint32_t a;
    asm("{ .reg .u64 t; cvta.to.shared.u64 t, %1; cvt.u32.u64 %0, t; }"
        : "=r"(a) : "l"(p));
    return a;
}

// ---------------- prep kernels (R9-proven) ------------------------------------
__global__ void detect_dtype(const unsigned* __restrict__ et_words) {
    int is64 = 1;
    for (int i = 0; i < 64; ++i) {
        unsigned lo = et_words[2 * i], hi = et_words[2 * i + 1];
        if (hi != 0u || lo >= (unsigned)RREL) { is64 = 0; break; }
    }
    g_is64 = is64;
}
__global__ void zero_M(int also_cnt) {
    size_t i = (size_t)blockIdx.x * 256 + threadIdx.x;
    size_t n4 = (size_t)NNODES * RREL * 64;
    if (i < n4) ((float4*)g_M)[i] = make_float4(0.f, 0.f, 0.f, 0.f);
    if (also_cnt && i < NSEG) g_cnt[i] = 0;
}
__global__ void prep_edges(const void* __restrict__ ei_raw,
                           const void* __restrict__ et_raw) {
    int e = blockIdx.x * 256 + threadIdx.x;
    if (e >= NEDGES) return;
    int s, d, t;
    if (g_is64) {
        const long long* ei = (const long long*)ei_raw;
        const long long* et = (const long long*)et_raw;
        s = (int)ei[e]; d = (int)ei[NEDGES + e]; t = (int)et[e];
    } else {
        const int* ei = (const int*)ei_raw;
        const int* et = (const int*)et_raw;
        s = ei[e];      d = ei[NEDGES + e];      t = et[e];
    }
    s = min(max(s, 0), NNODES - 1);
    d = min(max(d, 0), NNODES - 1);
    t = min(max(t, 0), RREL - 1);
    g_src[e] = s;
    int g = d * RREL + t;
    g_seg[e] = g;
    atomicAdd(&g_cnt[g], 1);
}
__global__ void make_inv() {
    int i = blockIdx.x * 256 + threadIdx.x;
    if (i < NSEG) g_inv[i] = 1.0f / fmaxf((float)g_cnt[i], 1.0f);
}

// W[k=r*256+i][o] = sum_b comp[r,b]*bases[b,i,o]; stored transposed+split Wt[o][k]
__global__ void build_W(const float* __restrict__ bases,
                        const float* __restrict__ comp, int layer) {
    const int ncols = (layer == 1) ? HID : Z_DIM;
    const int IO = 256 * ncols;
    __nv_bfloat16* Wh = (layer == 1) ? g_W1h : g_W2h;
    __nv_bfloat16* Wl = (layer == 1) ? g_W1l : g_W2l;
    __shared__ float sc[RREL * NBASES];
    if (threadIdx.x < RREL * NBASES) sc[threadIdx.x] = comp[threadIdx.x];
    __syncthreads();
    int io = blockIdx.x * 256 + threadIdx.x;
    if (io >= IO) return;
    int i = io / ncols, o = io % ncols;
    float acc[RREL];
#pragma unroll
    for (int r = 0; r < RREL; ++r) acc[r] = 0.f;
#pragma unroll 5
    for (int b = 0; b < NBASES; ++b) {
        float bv = bases[(size_t)b * IO + io];
#pragma unroll
        for (int r = 0; r < RREL; ++r) acc[r] += sc[r * NBASES + b] * bv;
    }
#pragma unroll
    for (int r = 0; r < RREL; ++r) {
        __nv_bfloat16 h, l; split_bf(acc[r], h, l);
        size_t dst = (size_t)o * KAGG + r * 256 + i;
        Wh[dst] = h; Wl[dst] = l;
    }
}
__global__ void build_root(const float* __restrict__ root, int layer) {
    const int ncols = (layer == 1) ? HID : Z_DIM;
    int io = blockIdx.x * 256 + threadIdx.x;
    if (io >= 256 * ncols) return;
    int i = io / ncols, o = io % ncols;
    __nv_bfloat16 h, l; split_bf(root[io], h, l);
    __nv_bfloat16* Rh = (layer == 1) ? g_R1h : g_R2h;
    __nv_bfloat16* Rl = (layer == 1) ? g_R1l : g_R2l;
    Rh[(size_t)o * 256 + i] = h; Rl[(size_t)o * 256 + i] = l;
}

// scatter (R9): g_M[seg,:] += inv[seg] * feat[src,:]
__global__ void scatter_edges(const float* __restrict__ x, int use_z1) {
    const float* feat = use_z1 ? g_Z1 : x;
    int e = blockIdx.x * 4 + (threadIdx.x >> 6);
    int lane = threadIdx.x & 63;
    if (e >= NEDGES) return;
    int sg = g_seg[e];
    float sc = g_inv[sg];
    float4 v = *(const float4*)(feat + (size_t)g_src[e] * 256 + lane * 4);
    float* dst = g_M + (size_t)sg * 256 + lane * 4;
    atomicAdd(dst + 0, v.x * sc);
    atomicAdd(dst + 1, v.y * sc);
    atomicAdd(dst + 2, v.z * sc);
    atomicAdd(dst + 3, v.w * sc);
}

// ---------------- mma.sync dual-GEMM (bf16 3-term, ldmatrix) ------------------
// C[n,:] = g_M[n,:2048]@W + A2[n,:256]@root + bias (+leaky layer1)
// BM=128, BN=128, BK=32, 256 thr, 8 warps (4Mx2N), warp tile 32x64.
#define SSTR 40          // bf16 elems per smem row: 80B stride (16B-aligned)

#define MMA_BF16(d, a, b0v, b1v)                                            \
    asm volatile(                                                           \
        "mma.sync.aligned.m16n8k16.row.col.f32.bf16.bf16.f32 "              \
        "{%0,%1,%2,%3}, {%4,%5,%6,%7}, {%8,%9}, {%0,%1,%2,%3};"             \
        : "+f"(d[0]), "+f"(d[1]), "+f"(d[2]), "+f"(d[3])                    \
        : "r"(a[0]), "r"(a[1]), "r"(a[2]), "r"(a[3]), "r"(b0v), "r"(b1v))

#define LDSM_X4(r, addr)                                                    \
    asm volatile("ldmatrix.sync.aligned.m8n8.x4.shared.b16 {%0,%1,%2,%3}, [%4];" \
        : "=r"((r)[0]), "=r"((r)[1]), "=r"((r)[2]), "=r"((r)[3]) : "r"(addr))

__global__ __launch_bounds__(256, 2)
void gemm_mma(int layer, const float* __restrict__ xin,
              const float* __restrict__ bias, float* __restrict__ outp)
{
    __shared__ __align__(16) __nv_bfloat16 sAh[128][SSTR], sAl[128][SSTR];
    __shared__ __align__(16) __nv_bfloat16 sBh[128][SSTR], sBl[128][SSTR];

    const int ncols = (layer == 1) ? 256 : 128;
    const __nv_bfloat16* Wh = (layer == 1) ? g_W1h : g_W2h;
    const __nv_bfloat16* Wl = (layer == 1) ? g_W1l : g_W2l;
    const __nv_bfloat16* Rh = (layer == 1) ? g_R1h : g_R2h;
    const __nv_bfloat16* Rl = (layer == 1) ? g_R1l : g_R2l;
    const float* A2 = (layer == 1) ? xin : g_Z1;
    float*       C  = (layer == 1) ? g_Z1 : outp;
    const int leaky = (layer == 1);

    const int tid  = threadIdx.x;
    const int wid  = tid >> 5;
    const int lane = tid & 31;
    const int qg   = lane >> 2;
    const int tg   = lane & 3;
    const int wm   = (wid & 3) * 32;
    const int wn   = (wid >> 2) * 64;
    const int row0 = blockIdx.x * 128;
    const int col0 = blockIdx.y * 128;

    const uint32_t uAh = smem_u32(&sAh[0][0]), uAl = smem_u32(&sAl[0][0]);
    const uint32_t uBh = smem_u32(&sBh[0][0]), uBl = smem_u32(&sBl[0][0]);
    const uint32_t aoff = (uint32_t)(lane & 15) * (SSTR * 2) + ((lane >> 4) & 1) * 16;
    const uint32_t boff = (uint32_t)((lane & 7) + ((lane >> 4) & 1) * 8) * (SSTR * 2)
                        + ((lane >> 3) & 1) * 16;

    float acc[2][8][4];
#pragma unroll
    for (int mt = 0; mt < 2; ++mt)
#pragma unroll
        for (int nt = 0; nt < 8; ++nt)
#pragma unroll
            for (int i = 0; i < 4; ++i) acc[mt][nt][i] = 0.f;

    const int nchunkM = KAGG / 32;          // 64
    const int nchunks = nchunkM + 256 / 32; // 72

    for (int ic = 0; ic < nchunks; ++ic) {
        const float* A; int Ast, k0;
        const __nv_bfloat16 *Bh, *Bl; int Bst;
        if (ic < nchunkM) {
            A = g_M; Ast = KAGG; k0 = ic * 32;
            Bh = Wh; Bl = Wl; Bst = KAGG;
        } else {
            A = A2; Ast = 256; k0 = (ic - nchunkM) * 32;
            Bh = Rh; Bl = Rl; Bst = 256;
        }
        // ---- A: 128 rows x 32 floats -> split bf16 ---------------------------
#pragma unroll
        for (int it = 0; it < 4; ++it) {
            int idx = tid + it * 256;         // 0..1023
            int ar  = idx >> 3;               // 0..127
            int ac  = (idx & 7) * 4;          // 0..28
            float4 v = make_float4(0.f, 0.f, 0.f, 0.f);
            int gr = row0 + ar;
            if (gr < NNODES) v = *(const float4*)&A[(size_t)gr * Ast + k0 + ac];
            __nv_bfloat16 h0, h1, h2, h3, l0, l1, l2, l3;
            split_bf(v.x, h0, l0); split_bf(v.y, h1, l1);
            split_bf(v.z, h2, l2); split_bf(v.w, h3, l3);
            *(__nv_bfloat162*)&sAh[ar][ac]     = __nv_bfloat162(h0, h1);
            *(__nv_bfloat162*)&sAh[ar][ac + 2] = __nv_bfloat162(h2, h3);
            *(__nv_bfloat162*)&sAl[ar][ac]     = __nv_bfloat162(l0, l1);
            *(__nv_bfloat162*)&sAl[ar][ac + 2] = __nv_bfloat162(l2, l3);
        }
        // ---- B: 128 out-rows x 32 bf16 (pre-split in gmem) -------------------
#pragma unroll
        for (int it = 0; it < 2; ++it) {
            int idx = tid + it * 256;         // 0..511
            int n   = idx >> 2;               // 0..127
            int sgo = (idx & 3) * 16;         // byte within 64B row
            size_t gb = 2 * ((size_t)(col0 + n) * Bst + k0) + sgo;
            *(uint4*)((char*)&sBh[n][0] + sgo) = *(const uint4*)((const char*)Bh + gb);
            *(uint4*)((char*)&sBl[n][0] + sgo) = *(const uint4*)((const char*)Bl + gb);
        }
        __syncthreads();

        // ---- compute: 2 k16 steps -------------------------------------------
#pragma unroll
        for (int kt = 0; kt < 2; ++kt) {
            const uint32_t kb = kt * 32;
            uint32_t ah[2][4], al[2][4];
#pragma unroll
            for (int mt = 0; mt < 2; ++mt) {
                uint32_t ra = (uint32_t)(wm + mt * 16) * (SSTR * 2) + aoff + kb;
                LDSM_X4(ah[mt], uAh + ra);
                LDSM_X4(al[mt], uAl + ra);
            }
#pragma unroll
            for (int p = 0; p < 4; ++p) {
                uint32_t rb = (uint32_t)(wn + p * 16) * (SSTR * 2) + boff + kb;
                uint32_t bh[4], bl[4];
                LDSM_X4(bh, uBh + rb);
                LDSM_X4(bl, uBl + rb);
#pragma unroll
                for (int mt = 0; mt < 2; ++mt) {
                    MMA_BF16(acc[mt][2 * p],     ah[mt], bh[0], bh[1]);
                    MMA_BF16(acc[mt][2 * p],     ah[mt], bl[0], bl[1]);
                    MMA_BF16(acc[mt][2 * p],     al[mt], bh[0], bh[1]);
                    MMA_BF16(acc[mt][2 * p + 1], ah[mt], bh[2], bh[3]);
                    MMA_BF16(acc[mt][2 * p + 1], ah[mt], bl[2], bl[3]);
                    MMA_BF16(acc[mt][2 * p + 1], al[mt], bh[2], bh[3]);
                }
            }
        }
        __syncthreads();
    }

    // ---- epilogue (R11-validated fragment mapping) ---------------------------
#pragma unroll
    for (int mt = 0; mt < 2; ++mt) {
        int r0 = row0 + wm + mt * 16 + qg;
#pragma unroll
        for (int nt = 0; nt < 8; ++nt) {
            int c = col0 + wn + nt * 8 + 2 * tg;
            float b0 = bias[c], b1 = bias[c + 1];
            float v0 = acc[mt][nt][0] + b0;
            float v1 = acc[mt][nt][1] + b1;
            float v2 = acc[mt][nt][2] + b0;
            float v3 = acc[mt][nt][3] + b1;
            if (leaky) {
                v0 = v0 > 0.f ? v0 : 0.01f * v0;
                v1 = v1 > 0.f ? v1 : 0.01f * v1;
                v2 = v2 > 0.f ? v2 : 0.01f * v2;
                v3 = v3 > 0.f ? v3 : 0.01f * v3;
            }
            if (r0 < NNODES) {
                C[(size_t)r0 * ncols + c]     = v0;
                C[(size_t)r0 * ncols + c + 1] = v1;
            }
            if (r0 + 8 < NNODES) {
                C[(size_t)(r0 + 8) * ncols + c]     = v2;
                C[(size_t)(r0 + 8) * ncols + c + 1] = v3;
            }
        }
    }
}

// ---------------- host -------------------------------------------------------
static const void* find_in(void* const* d_in, const int* sz, int n_in,
                           int want, int occ, int fallback_idx) {
    int seen = 0;
    for (int i = 0; i < n_in; ++i) {
        if (sz[i] == want) {
            if (seen == occ) return d_in[i];
            ++seen;
        }
    }
    return d_in[fallback_idx];
}

extern "C" void kernel_launch(void* const* d_in, const int* in_sizes, int n_in,
                              void* d_out, int out_size) {
    const float* x      = (const float*)find_in(d_in, in_sizes, n_in, NNODES * IN_DIM,       0, 0);
    const void*  ei     =               find_in(d_in, in_sizes, n_in, 2 * NEDGES,            0, 1);
    const void*  et     =               find_in(d_in, in_sizes, n_in, NEDGES,                0, 2);
    const float* bases1 = (const float*)find_in(d_in, in_sizes, n_in, NBASES * IN_DIM * HID, 0, 3);
    const float* comp1  = (const float*)find_in(d_in, in_sizes, n_in, RREL * NBASES,         0, 4);
    const float* root1  = (const float*)find_in(d_in, in_sizes, n_in, IN_DIM * HID,          0, 5);
    const float* bias1  = (const float*)find_in(d_in, in_sizes, n_in, HID,                   0, 6);
    const float* bases2 = (const float*)find_in(d_in, in_sizes, n_in, NBASES * HID * Z_DIM,  0, 7);
    const float* comp2  = (const float*)find_in(d_in, in_sizes, n_in, RREL * NBASES,         1, 8);
    const float* root2  = (const float*)find_in(d_in, in_sizes, n_in, HID * Z_DIM,           0, 9);
    const float* bias2  = (const float*)find_in(d_in, in_sizes, n_in, Z_DIM,                 0, 10);
    float* out = (float*)d_out;

    const int n4 = NNODES * RREL * 64;
    const int gZ = (n4 + 255) / 256;

    // prep
    detect_dtype<<<1, 1>>>((const unsigned*)et);
    zero_M<<<gZ, 256>>>(1);
    prep_edges<<<(NEDGES + 255) / 256, 256>>>(ei, et);
    make_inv<<<(NSEG + 255) / 256, 256>>>();
    build_W<<<(IN_DIM * HID + 255) / 256, 256>>>(bases1, comp1, 1);
    build_W<<<(HID * Z_DIM + 255) / 256, 256>>>(bases2, comp2, 2);
    build_root<<<(IN_DIM * HID + 255) / 256, 256>>>(root1, 1);
    build_root<<<(HID * Z_DIM + 255) / 256, 256>>>(root2, 2);

    // layer 1
    scatter_edges<<<NEDGES / 4, 256>>>(x, 0);
    {
        dim3 grid((NNODES + 127) / 128, 2);
        gemm_mma<<<grid, 256>>>(1, x, bias1, out);
    }

    // layer 2
    zero_M<<<gZ, 256>>>(0);
    scatter_edges<<<NEDGES / 4, 256>>>(x, 1);
    {
        dim3 grid((NNODES + 127) / 128, 1);
        gemm_mma<<<grid, 256>>>(2, x, bias2, out);
    }
}

// round 15
// speedup vs baseline: 4.0744x; 1.7888x over previous
#include <cuda_runtime.h>
#include <cuda_bf16.h>
#include <cstdint>

// Problem constants
#define NNODES   30000
#define RREL     8
#define NBASES   30
#define IN_DIM   256
#define Z_DIM    128
#define HID      256
#define NEDGES   480000
#define NSEG     (NNODES*RREL)
#define SCAN_B   1024
#define NBLK_D   ((NNODES + SCAN_B - 1) / SCAN_B)   // 30

// ---------------- device scratch ---------------------------------------------
__device__ __align__(16) float g_M [(size_t)NNODES * 2048];   // xall buffer, 245.76 MB
__device__ __align__(16) float g_Z1[(size_t)NNODES * HID];
__device__ __align__(16) float g_inv[NSEG];
__device__ int g_cnt  [NSEG];      // per-(dst,rel) counts (for mean)
__device__ int g_cntd [NNODES];    // per-dst counts (for CSR)
__device__ int g_offd [NNODES];
__device__ int g_filld[NNODES];
__device__ int g_dst  [NEDGES];
__device__ int g_srcet[NEDGES];    // src*8 + et
__device__ int g_epk  [NEDGES];    // src*8+et, sorted by dst
__device__ int g_bsum[32], g_bpre[32];
__device__ int g_is64;
// pre-split weights, B-operand layout [outCol][K=256] K-major bf16
__device__ __align__(16) __nv_bfloat16 g_W1h[2048*256], g_W1l[2048*256];
__device__ __align__(16) __nv_bfloat16 g_W2h[1024*256], g_W2l[1024*256];
__device__ __align__(16) __nv_bfloat16 g_R1h[256*256],  g_R1l[256*256];
__device__ __align__(16) __nv_bfloat16 g_R2h[128*256],  g_R2l[128*256];

__device__ __forceinline__ void split_bf(float v, __nv_bfloat16& h, __nv_bfloat16& l) {
    h = __float2bfloat16(v);
    l = __float2bfloat16(v - __bfloat162float(h));
}
__device__ __forceinline__ uint32_t smem_u32(const void* p) {
    uint32_t a;
    asm("{ .reg .u64 t; cvta.to.shared.u64 t, %1; cvt.u32.u64 %0, t; }"
        : "=r"(a) : "l"(p));
    return a;
}

// ---------------- prep kernels ------------------------------------------------
__global__ void detect_dtype(const unsigned* __restrict__ et_words) {
    int is64 = 1;
    for (int i = 0; i < 64; ++i) {
        unsigned lo = et_words[2 * i], hi = et_words[2 * i + 1];
        if (hi != 0u || lo >= (unsigned)RREL) { is64 = 0; break; }
    }
    g_is64 = is64;
}
__global__ void zero_counts() {
    int i = blockIdx.x * 256 + threadIdx.x;
    if (i < NSEG) g_cnt[i] = 0;
    if (i < NNODES) g_cntd[i] = 0;
}
__global__ void prep_edges(const void* __restrict__ ei_raw,
                           const void* __restrict__ et_raw) {
    int e = blockIdx.x * 256 + threadIdx.x;
    if (e >= NEDGES) return;
    int s, d, t;
    if (g_is64) {
        const long long* ei = (const long long*)ei_raw;
        const long long* et = (const long long*)et_raw;
        s = (int)ei[e]; d = (int)ei[NEDGES + e]; t = (int)et[e];
    } else {
        const int* ei = (const int*)ei_raw;
        const int* et = (const int*)et_raw;
        s = ei[e];      d = ei[NEDGES + e];      t = et[e];
    }
    s = min(max(s, 0), NNODES - 1);
    d = min(max(d, 0), NNODES - 1);
    t = min(max(t, 0), RREL - 1);
    g_dst[e] = d;
    g_srcet[e] = s * 8 + t;
    atomicAdd(&g_cnt[d * RREL + t], 1);
    atomicAdd(&g_cntd[d], 1);
}
__global__ void make_inv() {
    int i = blockIdx.x * 256 + threadIdx.x;
    if (i < NSEG) g_inv[i] = 1.0f / fmaxf((float)g_cnt[i], 1.0f);
}
// two-level exclusive scan over g_cntd (30000)
__global__ void scan_local() {
    __shared__ int sh[SCAN_B];
    int tid = threadIdx.x;
    int i = blockIdx.x * SCAN_B + tid;
    int v = (i < NNODES) ? g_cntd[i] : 0;
    sh[tid] = v;
    __syncthreads();
    for (int off = 1; off < SCAN_B; off <<= 1) {
        int t = 0;
        if (tid >= off) t = sh[tid - off];
        __syncthreads();
        if (tid >= off) sh[tid] += t;
        __syncthreads();
    }
    if (i < NNODES) g_offd[i] = sh[tid] - v;
    if (tid == SCAN_B - 1) g_bsum[blockIdx.x] = sh[tid];
}
__global__ void scan_blocks() {   // 32 threads
    __shared__ int sh[32];
    int tid = threadIdx.x;
    int v = (tid < NBLK_D) ? g_bsum[tid] : 0;
    sh[tid] = v;
    __syncthreads();
    for (int off = 1; off < 32; off <<= 1) {
        int t = 0;
        if (tid >= off) t = sh[tid - off];
        __syncthreads();
        if (tid >= off) sh[tid] += t;
        __syncthreads();
    }
    g_bpre[tid] = sh[tid] - v;
}
__global__ void scan_add_fill() {
    int i = blockIdx.x * 256 + threadIdx.x;
    if (i >= NNODES) return;
    int o = g_offd[i] + g_bpre[i >> 10];
    g_offd[i] = o;
    g_filld[i] = o;
}
__global__ void place_edges() {
    int e = blockIdx.x * 256 + threadIdx.x;
    if (e >= NEDGES) return;
    int pos = atomicAdd(&g_filld[g_dst[e]], 1);
    g_epk[pos] = g_srcet[e];
}

// Wcat B-operand: Bt[(r*outd+o)][i] = sum_b comp[r,b]*bases[b][i][o], split hi/lo
__global__ void build_W(const float* __restrict__ bases,
                        const float* __restrict__ comp, int layer) {
    const int outd = (layer == 1) ? HID : Z_DIM;
    const int IO = 256 * outd;
    __nv_bfloat16* Wh = (layer == 1) ? g_W1h : g_W2h;
    __nv_bfloat16* Wl = (layer == 1) ? g_W1l : g_W2l;
    __shared__ float sc[RREL * NBASES];
    if (threadIdx.x < RREL * NBASES) sc[threadIdx.x] = comp[threadIdx.x];
    __syncthreads();
    int io = blockIdx.x * 256 + threadIdx.x;
    if (io >= IO) return;
    int i = io / outd, o = io % outd;
    float acc[RREL];
#pragma unroll
    for (int r = 0; r < RREL; ++r) acc[r] = 0.f;
#pragma unroll 5
    for (int b = 0; b < NBASES; ++b) {
        float bv = bases[(size_t)b * IO + io];
#pragma unroll
        for (int r = 0; r < RREL; ++r) acc[r] += sc[r * NBASES + b] * bv;
    }
#pragma unroll
    for (int r = 0; r < RREL; ++r) {
        __nv_bfloat16 h, l; split_bf(acc[r], h, l);
        size_t dst = (size_t)(r * outd + o) * 256 + i;
        Wh[dst] = h; Wl[dst] = l;
    }
}
__global__ void build_root(const float* __restrict__ root, int layer) {
    const int outd = (layer == 1) ? HID : Z_DIM;
    int io = blockIdx.x * 256 + threadIdx.x;
    if (io >= 256 * outd) return;
    int i = io / outd, o = io % outd;
    __nv_bfloat16 h, l; split_bf(root[io], h, l);
    __nv_bfloat16* Rh = (layer == 1) ? g_R1h : g_R2h;
    __nv_bfloat16* Rl = (layer == 1) ? g_R1l : g_R2l;
    Rh[(size_t)o * 256 + i] = h; Rl[(size_t)o * 256 + i] = l;
}

// ---------------- mma.sync GEMM (bf16 3-term, ldmatrix), K=256 ----------------
// C[30000, ncols] = A[30000,256] @ Bt^T (+bias). BM=BN=128, BK=32, 8 warps.
#define SSTR 40

#define MMA_BF16(d, a, b0v, b1v)                                            \
    asm volatile(                                                           \
        "mma.sync.aligned.m16n8k16.row.col.f32.bf16.bf16.f32 "              \
        "{%0,%1,%2,%3}, {%4,%5,%6,%7}, {%8,%9}, {%0,%1,%2,%3};"             \
        : "+f"(d[0]), "+f"(d[1]), "+f"(d[2]), "+f"(d[3])                    \
        : "r"(a[0]), "r"(a[1]), "r"(a[2]), "r"(a[3]), "r"(b0v), "r"(b1v))

#define LDSM_X4(r, addr)                                                    \
    asm volatile("ldmatrix.sync.aligned.m8n8.x4.shared.b16 {%0,%1,%2,%3}, [%4];" \
        : "=r"((r)[0]), "=r"((r)[1]), "=r"((r)[2]), "=r"((r)[3]) : "r"(addr))

__global__ __launch_bounds__(256, 2)
void gemm_mma(const float* __restrict__ A,
              const __nv_bfloat16* __restrict__ Bh,
              const __nv_bfloat16* __restrict__ Bl,
              const float* __restrict__ bias,   // nullable
              float* __restrict__ C, int ncols)
{
    __shared__ __align__(16) __nv_bfloat16 sAh[128][SSTR], sAl[128][SSTR];
    __shared__ __align__(16) __nv_bfloat16 sBh[128][SSTR], sBl[128][SSTR];

    const int tid  = threadIdx.x;
    const int wid  = tid >> 5;
    const int lane = tid & 31;
    const int qg   = lane >> 2;
    const int tg   = lane & 3;
    const int wm   = (wid & 3) * 32;
    const int wn   = (wid >> 2) * 64;
    const int row0 = blockIdx.x * 128;
    const int col0 = blockIdx.y * 128;

    const uint32_t uAh = smem_u32(&sAh[0][0]), uAl = smem_u32(&sAl[0][0]);
    const uint32_t uBh = smem_u32(&sBh[0][0]), uBl = smem_u32(&sBl[0][0]);
    const uint32_t aoff = (uint32_t)(lane & 15) * (SSTR * 2) + ((lane >> 4) & 1) * 16;
    const uint32_t boff = (uint32_t)((lane & 7) + ((lane >> 4) & 1) * 8) * (SSTR * 2)
                        + ((lane >> 3) & 1) * 16;

    float acc[2][8][4];
#pragma unroll
    for (int mt = 0; mt < 2; ++mt)
#pragma unroll
        for (int nt = 0; nt < 8; ++nt)
#pragma unroll
            for (int i = 0; i < 4; ++i) acc[mt][nt][i] = 0.f;

#pragma unroll 1
    for (int ic = 0; ic < 8; ++ic) {
        const int k0 = ic * 32;
        // A tile: 128 rows x 32 floats -> split bf16
#pragma unroll
        for (int it = 0; it < 4; ++it) {
            int idx = tid + it * 256;
            int ar  = idx >> 3;
            int ac  = (idx & 7) * 4;
            float4 v = make_float4(0.f, 0.f, 0.f, 0.f);
            int gr = row0 + ar;
            if (gr < NNODES) v = *(const float4*)&A[(size_t)gr * 256 + k0 + ac];
            __nv_bfloat16 h0, h1, h2, h3, l0, l1, l2, l3;
            split_bf(v.x, h0, l0); split_bf(v.y, h1, l1);
            split_bf(v.z, h2, l2); split_bf(v.w, h3, l3);
            *(__nv_bfloat162*)&sAh[ar][ac]     = __nv_bfloat162(h0, h1);
            *(__nv_bfloat162*)&sAh[ar][ac + 2] = __nv_bfloat162(h2, h3);
            *(__nv_bfloat162*)&sAl[ar][ac]     = __nv_bfloat162(l0, l1);
            *(__nv_bfloat162*)&sAl[ar][ac + 2] = __nv_bfloat162(l2, l3);
        }
        // B tile: 128 out-cols x 32 bf16 (pre-split)
#pragma unroll
        for (int it = 0; it < 2; ++it) {
            int idx = tid + it * 256;
            int n   = idx >> 2;
            int sgo = (idx & 3) * 16;
            size_t gb = 2 * ((size_t)(col0 + n) * 256 + k0) + sgo;
            *(uint4*)((char*)&sBh[n][0] + sgo) = *(const uint4*)((const char*)Bh + gb);
            *(uint4*)((char*)&sBl[n][0] + sgo) = *(const uint4*)((const char*)Bl + gb);
        }
        __syncthreads();

#pragma unroll
        for (int kt = 0; kt < 2; ++kt) {
            const uint32_t kb = kt * 32;
            uint32_t ah[2][4], al[2][4];
#pragma unroll
            for (int mt = 0; mt < 2; ++mt) {
                uint32_t ra = (uint32_t)(wm + mt * 16) * (SSTR * 2) + aoff + kb;
                LDSM_X4(ah[mt], uAh + ra);
                LDSM_X4(al[mt], uAl + ra);
            }
#pragma unroll
            for (int p = 0; p < 4; ++p) {
                uint32_t rb = (uint32_t)(wn + p * 16) * (SSTR * 2) + boff + kb;
                uint32_t bh[4], bl[4];
                LDSM_X4(bh, uBh + rb);
                LDSM_X4(bl, uBl + rb);
#pragma unroll
                for (int mt = 0; mt < 2; ++mt) {
                    MMA_BF16(acc[mt][2 * p],     ah[mt], bh[0], bh[1]);
                    MMA_BF16(acc[mt][2 * p],     ah[mt], bl[0], bl[1]);
                    MMA_BF16(acc[mt][2 * p],     al[mt], bh[0], bh[1]);
                    MMA_BF16(acc[mt][2 * p + 1], ah[mt], bh[2], bh[3]);
                    MMA_BF16(acc[mt][2 * p + 1], ah[mt], bl[2], bl[3]);
                    MMA_BF16(acc[mt][2 * p + 1], al[mt], bh[2], bh[3]);
                }
            }
        }
        __syncthreads();
    }

    // epilogue: optional bias; fragment-mapped stores
#pragma unroll
    for (int mt = 0; mt < 2; ++mt) {
        int r0 = row0 + wm + mt * 16 + qg;
#pragma unroll
        for (int nt = 0; nt < 8; ++nt) {
            int c = col0 + wn + nt * 8 + 2 * tg;
            float b0 = bias ? bias[c] : 0.f;
            float b1 = bias ? bias[c + 1] : 0.f;
            float v0 = acc[mt][nt][0] + b0;
            float v1 = acc[mt][nt][1] + b1;
            float v2 = acc[mt][nt][2] + b0;
            float v3 = acc[mt][nt][3] + b1;
            if (r0 < NNODES) {
                C[(size_t)r0 * ncols + c]     = v0;
                C[(size_t)r0 * ncols + c + 1] = v1;
            }
            if (r0 + 8 < NNODES) {
                C[(size_t)(r0 + 8) * ncols + c]     = v2;
                C[(size_t)(r0 + 8) * ncols + c + 1] = v3;
            }
        }
    }
}

// ---------------- CSR-by-dst gather-add (no atomics) --------------------------
// C[d,:] += sum_{e in dst d} inv[d*8+et_e] * xall[src_e, et_e, :]; optional leaky.
// TPD threads per dst row (outd/4 float4 lanes).
template <int OUTD, int LEAKY>
__global__ void gather_add(const float* __restrict__ xall, float* __restrict__ C)
{
    const int TPD = OUTD / 4;
    const int DPB = 256 / TPD;
    int d = blockIdx.x * DPB + threadIdx.x / TPD;
    int lane = threadIdx.x % TPD;
    if (d >= NNODES) return;
    int base = g_offd[d], deg = g_cntd[d];
    float4 acc = make_float4(0.f, 0.f, 0.f, 0.f);
#pragma unroll 4
    for (int j = 0; j < deg; ++j) {
        int pk = g_epk[base + j];
        int src = pk >> 3, et = pk & 7;
        float sc = g_inv[d * 8 + et];
        float4 v = *(const float4*)&xall[(size_t)src * (8 * OUTD) + et * OUTD + lane * 4];
        acc.x += sc * v.x; acc.y += sc * v.y; acc.z += sc * v.z; acc.w += sc * v.w;
    }
    float4 c = *(float4*)&C[(size_t)d * OUTD + lane * 4];
    c.x += acc.x; c.y += acc.y; c.z += acc.z; c.w += acc.w;
    if (LEAKY) {
        c.x = c.x > 0.f ? c.x : 0.01f * c.x;
        c.y = c.y > 0.f ? c.y : 0.01f * c.y;
        c.z = c.z > 0.f ? c.z : 0.01f * c.z;
        c.w = c.w > 0.f ? c.w : 0.01f * c.w;
    }
    *(float4*)&C[(size_t)d * OUTD + lane * 4] = c;
}

// ---------------- host --------------------------------------------------------
static const void* find_in(void* const* d_in, const int* sz, int n_in,
                           int want, int occ, int fallback_idx) {
    int seen = 0;
    for (int i = 0; i < n_in; ++i) {
        if (sz[i] == want) {
            if (seen == occ) return d_in[i];
            ++seen;
        }
    }
    return d_in[fallback_idx];
}

extern "C" void kernel_launch(void* const* d_in, const int* in_sizes, int n_in,
                              void* d_out, int out_size) {
    const float* x      = (const float*)find_in(d_in, in_sizes, n_in, NNODES * IN_DIM,       0, 0);
    const void*  ei     =               find_in(d_in, in_sizes, n_in, 2 * NEDGES,            0, 1);
    const void*  et     =               find_in(d_in, in_sizes, n_in, NEDGES,                0, 2);
    const float* bases1 = (const float*)find_in(d_in, in_sizes, n_in, NBASES * IN_DIM * HID, 0, 3);
    const float* comp1  = (const float*)find_in(d_in, in_sizes, n_in, RREL * NBASES,         0, 4);
    const float* root1  = (const float*)find_in(d_in, in_sizes, n_in, IN_DIM * HID,          0, 5);
    const float* bias1  = (const float*)find_in(d_in, in_sizes, n_in, HID,                   0, 6);
    const float* bases2 = (const float*)find_in(d_in, in_sizes, n_in, NBASES * HID * Z_DIM,  0, 7);
    const float* comp2  = (const float*)find_in(d_in, in_sizes, n_in, RREL * NBASES,         1, 8);
    const float* root2  = (const float*)find_in(d_in, in_sizes, n_in, HID * Z_DIM,           0, 9);
    const float* bias2  = (const float*)find_in(d_in, in_sizes, n_in, Z_DIM,                 0, 10);
    float* out = (float*)d_out;

    float *Mp, *Z1p;
    {
        // direct device-symbol references inside kernels; host only needs
        // pointers for gemm C args — obtain via kernels' own globals:
        // (cudaGetSymbolAddress proved fine once dtype was fixed; use it)
        cudaGetSymbolAddress((void**)&Mp,  g_M);
        cudaGetSymbolAddress((void**)&Z1p, g_Z1);
    }
    __nv_bfloat16 *W1h, *W1l, *W2h, *W2l, *R1h, *R1l, *R2h, *R2l;
    cudaGetSymbolAddress((void**)&W1h, g_W1h);
    cudaGetSymbolAddress((void**)&W1l, g_W1l);
    cudaGetSymbolAddress((void**)&W2h, g_W2h);
    cudaGetSymbolAddress((void**)&W2l, g_W2l);
    cudaGetSymbolAddress((void**)&R1h, g_R1h);
    cudaGetSymbolAddress((void**)&R1l, g_R1l);
    cudaGetSymbolAddress((void**)&R2h, g_R2h);
    cudaGetSymbolAddress((void**)&R2l, g_R2l);

    // ---- prep ---------------------------------------------------------------
    detect_dtype<<<1, 1>>>((const unsigned*)et);
    zero_counts<<<(NSEG + 255) / 256, 256>>>();
    prep_edges<<<(NEDGES + 255) / 256, 256>>>(ei, et);
    make_inv<<<(NSEG + 255) / 256, 256>>>();
    scan_local<<<NBLK_D, SCAN_B>>>();
    scan_blocks<<<1, 32>>>();
    scan_add_fill<<<(NNODES + 255) / 256, 256>>>();
    place_edges<<<(NEDGES + 255) / 256, 256>>>();
    build_W<<<(IN_DIM * HID + 255) / 256, 256>>>(bases1, comp1, 1);
    build_W<<<(HID * Z_DIM + 255) / 256, 256>>>(bases2, comp2, 2);
    build_root<<<(IN_DIM * HID + 255) / 256, 256>>>(root1, 1);
    build_root<<<(HID * Z_DIM + 255) / 256, 256>>>(root2, 2);

    const int gx = (NNODES + 127) / 128;   // 235

    // ---- layer 1 ------------------------------------------------------------
    gemm_mma<<<dim3(gx, 16), 256>>>(x, W1h, W1l, nullptr, Mp, 2048);   // xall1
    gemm_mma<<<dim3(gx, 2),  256>>>(x, R1h, R1l, bias1,  Z1p, 256);    // root part
    gather_add<256, 1><<<(NNODES + 3) / 4, 256>>>(Mp, Z1p);            // +agg, leaky

    // ---- layer 2 ------------------------------------------------------------
    gemm_mma<<<dim3(gx, 8), 256>>>(Z1p, W2h, W2l, nullptr, Mp, 1024);  // xall2
    gemm_mma<<<dim3(gx, 1), 256>>>(Z1p, R2h, R2l, bias2,  out, 128);   // root part
    gather_add<128, 0><<<(NNODES + 7) / 8, 256>>>(Mp, out);            // +agg
}